// round 13
// baseline (speedup 1.0000x reference)
#include <cuda_runtime.h>
#include <cuda_fp16.h>
#include <cstdint>
#include <cstddef>

// ---------------- problem constants ----------------
#define S_TOK   8192
#define HDIM    1024
#define FDIM    4096
#define NEXP    8
#define NPAIR   16384              // S*K rows (one per (s,k) pair, no dedup)
#define ROWS_PAD 17408             // NPAIR + 8*127 rounded up
#define MTILE_MAX 144              // worst-case per-expert 128-row tiles (<=135)
#define CONV_ROWS 128              // extra grid.y rows in gemm1 that convert w2

// GEMM tile: BM=128, BN=256, BK=64, 4-stage cp.async pipeline, mma.sync core
// smem stage: A 128x128B + B 256x128B, XOR-swizzled 16B chunks (chunk ^= row&7)
#define A_STG  16384
#define STAGE_BYTES 49152
#define SMEM_TOTAL  (4 * STAGE_BYTES)          // 196608
// ---------------- device scratch (allocation-free rule) ----------------
__device__ __half g_xg  [(size_t)ROWS_PAD * HDIM];
__device__ __half g_hbuf[(size_t)ROWS_PAD * FDIM];
__device__ float  g_yh  [(size_t)ROWS_PAD * HDIM];
__device__ __half g_w1h [(size_t)NEXP * FDIM * HDIM];
__device__ __half g_w2h [(size_t)NEXP * FDIM * HDIM];
__device__ float  g_row_w[ROWS_PAD];
__device__ int    g_tok_rows[NPAIR];
__device__ int    g_base[NEXP];
__device__ int    g_fill[NEXP];
__device__ int    g_tile_e[MTILE_MAX];
__device__ int    g_tile_m[MTILE_MAX];
__device__ int    g_nmt;

// ---------------- PTX helpers ----------------
__device__ __forceinline__ uint32_t smem_u32(const void* p) {
    uint32_t a;
    asm("{ .reg .u64 t; cvta.to.shared.u64 t, %1; cvt.u32.u64 %0, t; }"
        : "=r"(a) : "l"(p));
    return a;
}

__device__ __forceinline__ void cp16(uint32_t dst, const void* src) {
    asm volatile("cp.async.cg.shared.global [%0], [%1], 16;"
                 :: "r"(dst), "l"(src));
}

__device__ __forceinline__ void ldsm4(uint32_t* r, uint32_t a) {
    asm volatile("ldmatrix.sync.aligned.m8n8.x4.shared.b16 {%0,%1,%2,%3}, [%4];"
                 : "=r"(r[0]), "=r"(r[1]), "=r"(r[2]), "=r"(r[3]) : "r"(a));
}

__device__ __forceinline__ void mma16816(float* c, const uint32_t* a,
                                         uint32_t b0, uint32_t b1) {
    asm volatile(
        "mma.sync.aligned.m16n8k16.row.col.f32.f16.f16.f32 "
        "{%0,%1,%2,%3}, {%4,%5,%6,%7}, {%8,%9}, {%0,%1,%2,%3};"
        : "+f"(c[0]), "+f"(c[1]), "+f"(c[2]), "+f"(c[3])
        : "r"(a[0]), "r"(a[1]), "r"(a[2]), "r"(a[3]), "r"(b0), "r"(b1));
}

// ---------------- routing (single block: zero + count + schedule) ----------------
__global__ void routing_kernel(const int* __restrict__ te) {
    __shared__ int scnt[NEXP];
    int tid = threadIdx.x;
    if (tid < NEXP) scnt[tid] = 0;
    __syncthreads();
    for (int t = tid; t < NPAIR; t += 256)
        atomicAdd(&scnt[((unsigned)te[t]) & 7u], 1);
    __syncthreads();
    if (tid == 0) {
        int base = 0, nt = 0;
        for (int e = 0; e < NEXP; e++) {
            g_base[e] = base;
            g_fill[e] = 0;
            int tiles = (scnt[e] + 127) >> 7;
            for (int t = 0; t < tiles; t++) {
                g_tile_e[nt] = e;
                g_tile_m[nt] = base + t * 128;
                nt++;
            }
            base += tiles << 7;
        }
        g_nmt = nt;
    }
}

__global__ void fill_kernel(const int* __restrict__ te, const float* __restrict__ tw) {
    int t = blockIdx.x * 256 + threadIdx.x;
    if (t < NPAIR) {
        int e = ((unsigned)te[t]) & 7u;
        int pos = atomicAdd(&g_fill[e], 1);
        int row = g_base[e] + pos;
        g_tok_rows[t] = row;
        g_row_w[row] = tw[t];
    }
}

// gather x rows (fp32 -> fp16) into grouped buffer; one block per (s,k) pair
__global__ void gather_kernel(const float* __restrict__ x) {
    int p = blockIdx.x;
    int j = threadIdx.x;                       // float4 index within row (256)
    int row = g_tok_rows[p];
    int s = p >> 1;
    float4 v = reinterpret_cast<const float4*>(x)[(size_t)s * 256 + j];
    __half2 a = __floats2half2_rn(v.x, v.y);
    __half2 b = __floats2half2_rn(v.z, v.w);
    uint2 u = make_uint2(*(uint32_t*)&a, *(uint32_t*)&b);
    *reinterpret_cast<uint2*>(&g_xg[(size_t)row * HDIM + j * 4]) = u;
}

// fp32 -> fp16 convert for w1 only (w2 is converted inside the gemm1 launch)
__global__ void convert_w1_kernel(const float* __restrict__ w1) {
    size_t i = (size_t)blockIdx.x * 256 + threadIdx.x;   // float4 index
    float4 v = reinterpret_cast<const float4*>(w1)[i];
    __half2 a = __floats2half2_rn(v.x, v.y);
    __half2 b = __floats2half2_rn(v.z, v.w);
    uint2 u = make_uint2(*(uint32_t*)&a, *(uint32_t*)&b);
    *reinterpret_cast<uint2*>(&g_w1h[i * 4]) = u;
}

// y[s] = yh[row(s,0)] + yh[row(s,1)]   (fixed order -> deterministic)
__global__ void combine_kernel(float* __restrict__ out) {
    int s = blockIdx.x, j = threadIdx.x;
    int r0 = g_tok_rows[2 * s];
    int r1 = g_tok_rows[2 * s + 1];
    const float4* Y = reinterpret_cast<const float4*>(g_yh);
    float4 a = Y[(size_t)r0 * 256 + j];
    float4 b = Y[(size_t)r1 * 256 + j];
    reinterpret_cast<float4*>(out)[(size_t)s * 256 + j] =
        make_float4(a.x + b.x, a.y + b.y, a.z + b.z, a.w + b.w);
}

// ---------------- grouped GEMM (mma.sync + cp.async, 128x256x64, 4 stages) ----------------
// mode 0: h = silu(Xg @ W1[e]^T) -> g_hbuf fp16    (lda=1024, kiter=16)
//         plus CONV_ROWS extra grid.y rows converting w2 fp32->fp16
// mode 1: y = (h @ W2[e]^T) * w  -> g_yh  fp32     (lda=4096, kiter=64)
__device__ __forceinline__ void load_stage(uint32_t stg, int chunk,
                                           const __half* A, const __half* B,
                                           int lda, int tid) {
    uint32_t base = stg + (uint32_t)(chunk & 3) * STAGE_BYTES;
    const __half* Ap = A + chunk * 64;
    const __half* Bp = B + chunk * 64;
#pragma unroll
    for (int i = 0; i < 4; i++) {                 // A: 128 rows x 8 x 16B chunks
        int q = i * 256 + tid;
        int r = q >> 3, c = q & 7;
        uint32_t dst = base + (uint32_t)(r * 128 + ((c ^ (r & 7)) << 4));
        cp16(dst, Ap + (size_t)r * lda + c * 8);
    }
#pragma unroll
    for (int i = 0; i < 8; i++) {                 // B: 256 rows x 8 x 16B chunks
        int q = i * 256 + tid;
        int r = q >> 3, c = q & 7;
        uint32_t dst = base + A_STG + (uint32_t)(r * 128 + ((c ^ (r & 7)) << 4));
        cp16(dst, Bp + (size_t)r * lda + c * 8);
    }
    asm volatile("cp.async.commit_group;" ::: "memory");
}

__global__ void __launch_bounds__(256, 1) gemm_kernel(int mode, const float* w2src) {
    // ---- fused w2 converter role (layer-1 launch only) ----
    if (mode == 0 && blockIdx.y >= MTILE_MAX) {
        size_t cid = (size_t)(blockIdx.y - MTILE_MAX) * gridDim.x + blockIdx.x;
        size_t tbase = cid * 256 + threadIdx.x;            // 0 .. 524287
        const float4* src = reinterpret_cast<const float4*>(w2src);
#pragma unroll 4
        for (int j = 0; j < 16; j++) {                     // 524288*16 = 8388608 float4
            size_t idx = tbase + (size_t)j * ((size_t)CONV_ROWS * 16 * 256);
            float4 v = src[idx];
            __half2 a = __floats2half2_rn(v.x, v.y);
            __half2 b = __floats2half2_rn(v.z, v.w);
            uint2 u = make_uint2(*(uint32_t*)&a, *(uint32_t*)&b);
            *reinterpret_cast<uint2*>(&g_w2h[idx * 4]) = u;
        }
        return;
    }

    int mt_idx = blockIdx.y;
    if (mt_idx >= g_nmt) return;

    const int lda   = mode ? FDIM : HDIM;
    const int kiter = mode ? (FDIM / 64) : (HDIM / 64);
    int m_base = g_tile_m[mt_idx];
    int n_base = blockIdx.x * 256;
    const __half* A = (mode ? g_hbuf : g_xg) + (size_t)m_base * lda;
    const __half* B = (mode ? g_w2h : g_w1h)
                      + (size_t)g_tile_e[mt_idx] * ((size_t)FDIM * HDIM)
                      + (size_t)n_base * lda;

    int tid = threadIdx.x;
    int wid = tid >> 5, lid = tid & 31;
    int warp_m = wid & 1;          // 2 along M  -> 64 rows each
    int warp_n = wid >> 1;         // 4 along N  -> 64 cols each

    extern __shared__ char smem[];
    uint32_t stg = smem_u32(smem);

    // ldmatrix lane addressing (same fragment mapping as the passing R10/R12 kernels)
    int ar = (lid & 7) + ((lid >> 3) & 1) * 8;   // row within 16-row tile
    int ac = (lid >> 4) & 1;                     // 16B k-chunk select
    int br = (lid & 7) + ((lid >> 4) & 1) * 8;   // row within 16-row n-pair
    int bc = (lid >> 3) & 1;

    float acc[4][8][4];
#pragma unroll
    for (int mt = 0; mt < 4; mt++)
#pragma unroll
        for (int nt = 0; nt < 8; nt++)
#pragma unroll
            for (int i = 0; i < 4; i++) acc[mt][nt][i] = 0.0f;

    // prologue: 3 stages in flight
    load_stage(stg, 0, A, B, lda, tid);
    load_stage(stg, 1, A, B, lda, tid);
    load_stage(stg, 2, A, B, lda, tid);

    for (int k = 0; k < kiter; k++) {
        if (k + 3 <= kiter - 1)      asm volatile("cp.async.wait_group 2;" ::: "memory");
        else if (k + 2 <= kiter - 1) asm volatile("cp.async.wait_group 1;" ::: "memory");
        else                         asm volatile("cp.async.wait_group 0;" ::: "memory");
        __syncthreads();

        if (k + 3 < kiter) load_stage(stg, k + 3, A, B, lda, tid);

        uint32_t a_s = stg + (uint32_t)(k & 3) * STAGE_BYTES;
        uint32_t b_s = a_s + A_STG;

#pragma unroll
        for (int ks = 0; ks < 4; ks++) {          // four k16 steps per BK=64
            uint32_t af[4][4];
#pragma unroll
            for (int mt = 0; mt < 4; mt++) {
                int row = warp_m * 64 + mt * 16 + ar;
                int ch  = (ks * 2 + ac) ^ (row & 7);
                ldsm4(af[mt], a_s + (uint32_t)(row * 128 + (ch << 4)));
            }
            uint32_t bf[4][4];                    // each x4 covers 2 n-tiles
#pragma unroll
            for (int np = 0; np < 4; np++) {
                int row = warp_n * 64 + np * 16 + br;
                int ch  = (ks * 2 + bc) ^ (row & 7);
                ldsm4(bf[np], b_s + (uint32_t)(row * 128 + (ch << 4)));
            }
#pragma unroll
            for (int mt = 0; mt < 4; mt++) {
#pragma unroll
                for (int nt = 0; nt < 8; nt++) {
                    mma16816(acc[mt][nt], af[mt],
                             bf[nt >> 1][(nt & 1) * 2],
                             bf[nt >> 1][(nt & 1) * 2 + 1]);
                }
            }
        }
    }
    __syncthreads();

    // ---------------- epilogue ----------------
    int rbase = m_base + warp_m * 64;
    int cbase = n_base + warp_n * 64;
    int rl = lid >> 2;                  // 0..7
    int cl = (lid & 3) * 2;             // 0,2,4,6

    if (mode == 0) {
#pragma unroll
        for (int mt = 0; mt < 4; mt++) {
            int r0 = rbase + mt * 16 + rl;
#pragma unroll
            for (int nt = 0; nt < 8; nt++) {
                int c = cbase + nt * 8 + cl;
                float v0 = acc[mt][nt][0], v1 = acc[mt][nt][1];
                float v2 = acc[mt][nt][2], v3 = acc[mt][nt][3];
                v0 = v0 / (1.0f + __expf(-v0));
                v1 = v1 / (1.0f + __expf(-v1));
                v2 = v2 / (1.0f + __expf(-v2));
                v3 = v3 / (1.0f + __expf(-v3));
                __half2 h01 = __floats2half2_rn(v0, v1);
                __half2 h23 = __floats2half2_rn(v2, v3);
                *reinterpret_cast<__half2*>(&g_hbuf[(size_t)r0 * FDIM + c]) = h01;
                *reinterpret_cast<__half2*>(&g_hbuf[(size_t)(r0 + 8) * FDIM + c]) = h23;
            }
        }
    } else {
#pragma unroll
        for (int mt = 0; mt < 4; mt++) {
            int r0 = rbase + mt * 16 + rl;
            float w0 = g_row_w[r0];
            float w1 = g_row_w[r0 + 8];
#pragma unroll
            for (int nt = 0; nt < 8; nt++) {
                int c = cbase + nt * 8 + cl;
                float2 p0 = make_float2(acc[mt][nt][0] * w0, acc[mt][nt][1] * w0);
                float2 p1 = make_float2(acc[mt][nt][2] * w1, acc[mt][nt][3] * w1);
                *reinterpret_cast<float2*>(&g_yh[(size_t)r0 * HDIM + c]) = p0;
                *reinterpret_cast<float2*>(&g_yh[(size_t)(r0 + 8) * HDIM + c]) = p1;
            }
        }
    }
}

// ---------------- launch ----------------
extern "C" void kernel_launch(void* const* d_in, const int* in_sizes, int n_in,
                              void* d_out, int out_size) {
    const float* x  = (const float*)d_in[0];
    const int*   te = (const int*)d_in[1];
    const float* tw = (const float*)d_in[2];
    const float* w1 = (const float*)d_in[3];
    const float* w2 = (const float*)d_in[4];
    float* out = (float*)d_out;

    cudaFuncSetAttribute(gemm_kernel, cudaFuncAttributeMaxDynamicSharedMemorySize,
                         SMEM_TOTAL);

    routing_kernel<<<1, 256>>>(te);
    fill_kernel<<<NPAIR / 256, 256>>>(te, tw);
    gather_kernel<<<NPAIR, 256>>>(x);
    convert_w1_kernel<<<32768, 256>>>(w1);    // 8*4096*1024/4 float4s
    // layer-1 GEMM + fused w2 conversion (extra grid.y rows)
    gemm_kernel<<<dim3(FDIM / 256, MTILE_MAX + CONV_ROWS), 256, SMEM_TOTAL>>>(0, w2);
    gemm_kernel<<<dim3(HDIM / 256, MTILE_MAX), 256, SMEM_TOTAL>>>(1, w2);
    combine_kernel<<<S_TOK, 256>>>(out);
}

// round 14
// speedup vs baseline: 1.1690x; 1.1690x over previous
#include <cuda_runtime.h>
#include <cuda_fp16.h>
#include <cstdint>
#include <cstddef>

// ---------------- problem constants ----------------
#define S_TOK   8192
#define HDIM    1024
#define FDIM    4096
#define NEXP    8
#define NPAIR   16384              // S*K rows (one per (s,k) pair, no dedup)
#define ROWS_PAD 17408             // NPAIR + 8*127 rounded up
#define MTILE_MAX 144              // worst-case per-expert 128-row tiles (<=135)
#define CONV_ROWS 128              // extra grid.y rows in gemm1 that convert w2

// GEMM tile: BM=128, BN=128, BK=64, 3-stage cp.async pipeline, mma.sync core
// 4 warps (128 threads), warp tile 64x64 -> tensor-bound with smem headroom, occ 2
// smem stage: A 128x128B + B 128x128B, XOR-swizzled 16B chunks (chunk ^= row&7)
#define A_STG  16384
#define STAGE_BYTES 32768
#define SMEM_TOTAL  (3 * STAGE_BYTES)          // 98304

// ---------------- device scratch (allocation-free rule) ----------------
__device__ __half g_xg  [(size_t)ROWS_PAD * HDIM];
__device__ __half g_hbuf[(size_t)ROWS_PAD * FDIM];
__device__ float  g_yh  [(size_t)ROWS_PAD * HDIM];
__device__ __half g_w1h [(size_t)NEXP * FDIM * HDIM];
__device__ __half g_w2h [(size_t)NEXP * FDIM * HDIM];
__device__ float  g_row_w[ROWS_PAD];
__device__ int    g_tok_rows[NPAIR];
__device__ int    g_base[NEXP];
__device__ int    g_fill[NEXP];
__device__ int    g_tile_e[MTILE_MAX];
__device__ int    g_tile_m[MTILE_MAX];
__device__ int    g_nmt;

// ---------------- PTX helpers ----------------
__device__ __forceinline__ uint32_t smem_u32(const void* p) {
    uint32_t a;
    asm("{ .reg .u64 t; cvta.to.shared.u64 t, %1; cvt.u32.u64 %0, t; }"
        : "=r"(a) : "l"(p));
    return a;
}

__device__ __forceinline__ void cp16(uint32_t dst, const void* src) {
    asm volatile("cp.async.cg.shared.global [%0], [%1], 16;"
                 :: "r"(dst), "l"(src));
}

__device__ __forceinline__ void ldsm4(uint32_t* r, uint32_t a) {
    asm volatile("ldmatrix.sync.aligned.m8n8.x4.shared.b16 {%0,%1,%2,%3}, [%4];"
                 : "=r"(r[0]), "=r"(r[1]), "=r"(r[2]), "=r"(r[3]) : "r"(a));
}

__device__ __forceinline__ void mma16816(float* c, const uint32_t* a,
                                         uint32_t b0, uint32_t b1) {
    asm volatile(
        "mma.sync.aligned.m16n8k16.row.col.f32.f16.f16.f32 "
        "{%0,%1,%2,%3}, {%4,%5,%6,%7}, {%8,%9}, {%0,%1,%2,%3};"
        : "+f"(c[0]), "+f"(c[1]), "+f"(c[2]), "+f"(c[3])
        : "r"(a[0]), "r"(a[1]), "r"(a[2]), "r"(a[3]), "r"(b0), "r"(b1));
}

// ---------------- routing (single block: zero + count + schedule) ----------------
__global__ void routing_kernel(const int* __restrict__ te) {
    __shared__ int scnt[NEXP];
    int tid = threadIdx.x;
    if (tid < NEXP) scnt[tid] = 0;
    __syncthreads();
    for (int t = tid; t < NPAIR; t += 256)
        atomicAdd(&scnt[((unsigned)te[t]) & 7u], 1);
    __syncthreads();
    if (tid == 0) {
        int base = 0, nt = 0;
        for (int e = 0; e < NEXP; e++) {
            g_base[e] = base;
            g_fill[e] = 0;
            int tiles = (scnt[e] + 127) >> 7;
            for (int t = 0; t < tiles; t++) {
                g_tile_e[nt] = e;
                g_tile_m[nt] = base + t * 128;
                nt++;
            }
            base += tiles << 7;
        }
        g_nmt = nt;
    }
}

__global__ void fill_kernel(const int* __restrict__ te, const float* __restrict__ tw) {
    int t = blockIdx.x * 256 + threadIdx.x;
    if (t < NPAIR) {
        int e = ((unsigned)te[t]) & 7u;
        int pos = atomicAdd(&g_fill[e], 1);
        int row = g_base[e] + pos;
        g_tok_rows[t] = row;
        g_row_w[row] = tw[t];
    }
}

// gather x rows (fp32 -> fp16) into grouped buffer; one block per (s,k) pair
__global__ void gather_kernel(const float* __restrict__ x) {
    int p = blockIdx.x;
    int j = threadIdx.x;                       // float4 index within row (256)
    int row = g_tok_rows[p];
    int s = p >> 1;
    float4 v = reinterpret_cast<const float4*>(x)[(size_t)s * 256 + j];
    __half2 a = __floats2half2_rn(v.x, v.y);
    __half2 b = __floats2half2_rn(v.z, v.w);
    uint2 u = make_uint2(*(uint32_t*)&a, *(uint32_t*)&b);
    *reinterpret_cast<uint2*>(&g_xg[(size_t)row * HDIM + j * 4]) = u;
}

// fp32 -> fp16 convert for w1 only (w2 is converted inside the gemm1 launch)
__global__ void convert_w1_kernel(const float* __restrict__ w1) {
    size_t i = (size_t)blockIdx.x * 256 + threadIdx.x;   // float4 index
    float4 v = reinterpret_cast<const float4*>(w1)[i];
    __half2 a = __floats2half2_rn(v.x, v.y);
    __half2 b = __floats2half2_rn(v.z, v.w);
    uint2 u = make_uint2(*(uint32_t*)&a, *(uint32_t*)&b);
    *reinterpret_cast<uint2*>(&g_w1h[i * 4]) = u;
}

// y[s] = yh[row(s,0)] + yh[row(s,1)]   (fixed order -> deterministic)
__global__ void combine_kernel(float* __restrict__ out) {
    int s = blockIdx.x, j = threadIdx.x;
    int r0 = g_tok_rows[2 * s];
    int r1 = g_tok_rows[2 * s + 1];
    const float4* Y = reinterpret_cast<const float4*>(g_yh);
    float4 a = Y[(size_t)r0 * 256 + j];
    float4 b = Y[(size_t)r1 * 256 + j];
    reinterpret_cast<float4*>(out)[(size_t)s * 256 + j] =
        make_float4(a.x + b.x, a.y + b.y, a.z + b.z, a.w + b.w);
}

// ---------------- grouped GEMM (mma.sync + cp.async, BK=64, 3 stages, 4 warps) --------
// mode 0: h = silu(Xg @ W1[e]^T) -> g_hbuf fp16    (lda=1024, kiter=16)
//         plus CONV_ROWS extra grid.y rows converting w2 fp32->fp16
// mode 1: y = (h @ W2[e]^T) * w  -> g_yh  fp32     (lda=4096, kiter=64)
__device__ __forceinline__ void load_stage(uint32_t stg, int chunk,
                                           const __half* A, const __half* B,
                                           int lda, int tid) {
    uint32_t base = stg + (uint32_t)(chunk % 3) * STAGE_BYTES;
    const __half* Ap = A + chunk * 64;
    const __half* Bp = B + chunk * 64;
#pragma unroll
    for (int i = 0; i < 8; i++) {                 // A: 128 rows x 8 x 16B chunks
        int q = i * 128 + tid;
        int r = q >> 3, c = q & 7;
        uint32_t dst = base + (uint32_t)(r * 128 + ((c ^ (r & 7)) << 4));
        cp16(dst, Ap + (size_t)r * lda + c * 8);
    }
#pragma unroll
    for (int i = 0; i < 8; i++) {                 // B: 128 rows x 8 x 16B chunks
        int q = i * 128 + tid;
        int r = q >> 3, c = q & 7;
        uint32_t dst = base + A_STG + (uint32_t)(r * 128 + ((c ^ (r & 7)) << 4));
        cp16(dst, Bp + (size_t)r * lda + c * 8);
    }
    asm volatile("cp.async.commit_group;" ::: "memory");
}

__global__ void __launch_bounds__(128, 2) gemm_kernel(int mode, const float* w2src) {
    // ---- fused w2 converter role (layer-1 launch only) ----
    if (mode == 0 && blockIdx.y >= MTILE_MAX) {
        size_t cid = (size_t)(blockIdx.y - MTILE_MAX) * gridDim.x + blockIdx.x;
        size_t tbase = cid * 128 + threadIdx.x;            // 0 .. 524287
        const float4* src = reinterpret_cast<const float4*>(w2src);
#pragma unroll 4
        for (int j = 0; j < 16; j++) {                     // 524288*16 = 8388608 float4
            size_t idx = tbase + (size_t)j * ((size_t)CONV_ROWS * 32 * 128);
            float4 v = src[idx];
            __half2 a = __floats2half2_rn(v.x, v.y);
            __half2 b = __floats2half2_rn(v.z, v.w);
            uint2 u = make_uint2(*(uint32_t*)&a, *(uint32_t*)&b);
            *reinterpret_cast<uint2*>(&g_w2h[idx * 4]) = u;
        }
        return;
    }

    int mt_idx = blockIdx.y;
    if (mt_idx >= g_nmt) return;

    const int lda   = mode ? FDIM : HDIM;
    const int kiter = mode ? (FDIM / 64) : (HDIM / 64);
    int m_base = g_tile_m[mt_idx];
    int n_base = blockIdx.x * 128;
    const __half* A = (mode ? g_hbuf : g_xg) + (size_t)m_base * lda;
    const __half* B = (mode ? g_w2h : g_w1h)
                      + (size_t)g_tile_e[mt_idx] * ((size_t)FDIM * HDIM)
                      + (size_t)n_base * lda;

    int tid = threadIdx.x;
    int wid = tid >> 5, lid = tid & 31;
    int warp_m = wid & 1;          // 2 along M  -> 64 rows each
    int warp_n = wid >> 1;         // 2 along N  -> 64 cols each

    extern __shared__ char smem[];
    uint32_t stg = smem_u32(smem);

    // ldmatrix lane addressing (same fragment mapping as the passing R10/R12 kernels)
    int ar = (lid & 7) + ((lid >> 3) & 1) * 8;   // row within 16-row tile
    int ac = (lid >> 4) & 1;                     // 16B k-chunk select
    int br = (lid & 7) + ((lid >> 4) & 1) * 8;   // row within 16-row n-pair
    int bc = (lid >> 3) & 1;

    float acc[4][8][4];
#pragma unroll
    for (int mt = 0; mt < 4; mt++)
#pragma unroll
        for (int nt = 0; nt < 8; nt++)
#pragma unroll
            for (int i = 0; i < 4; i++) acc[mt][nt][i] = 0.0f;

    // prologue: 2 stages in flight
    load_stage(stg, 0, A, B, lda, tid);
    load_stage(stg, 1, A, B, lda, tid);

    for (int k = 0; k < kiter; k++) {
        if (k + 2 < kiter) asm volatile("cp.async.wait_group 1;" ::: "memory");
        else               asm volatile("cp.async.wait_group 0;" ::: "memory");
        __syncthreads();

        if (k + 2 < kiter) load_stage(stg, k + 2, A, B, lda, tid);

        uint32_t a_s = stg + (uint32_t)(k % 3) * STAGE_BYTES;
        uint32_t b_s = a_s + A_STG;

#pragma unroll
        for (int ks = 0; ks < 4; ks++) {          // four k16 steps per BK=64
            uint32_t af[4][4];
#pragma unroll
            for (int mt = 0; mt < 4; mt++) {
                int row = warp_m * 64 + mt * 16 + ar;
                int ch  = (ks * 2 + ac) ^ (row & 7);
                ldsm4(af[mt], a_s + (uint32_t)(row * 128 + (ch << 4)));
            }
            uint32_t bf[4][4];                    // each x4 covers 2 n-tiles
#pragma unroll
            for (int np = 0; np < 4; np++) {
                int row = warp_n * 64 + np * 16 + br;
                int ch  = (ks * 2 + bc) ^ (row & 7);
                ldsm4(bf[np], b_s + (uint32_t)(row * 128 + (ch << 4)));
            }
#pragma unroll
            for (int mt = 0; mt < 4; mt++) {
#pragma unroll
                for (int nt = 0; nt < 8; nt++) {
                    mma16816(acc[mt][nt], af[mt],
                             bf[nt >> 1][(nt & 1) * 2],
                             bf[nt >> 1][(nt & 1) * 2 + 1]);
                }
            }
        }
    }
    __syncthreads();

    // ---------------- epilogue ----------------
    int rbase = m_base + warp_m * 64;
    int cbase = n_base + warp_n * 64;
    int rl = lid >> 2;                  // 0..7
    int cl = (lid & 3) * 2;             // 0,2,4,6

    if (mode == 0) {
#pragma unroll
        for (int mt = 0; mt < 4; mt++) {
            int r0 = rbase + mt * 16 + rl;
#pragma unroll
            for (int nt = 0; nt < 8; nt++) {
                int c = cbase + nt * 8 + cl;
                float v0 = acc[mt][nt][0], v1 = acc[mt][nt][1];
                float v2 = acc[mt][nt][2], v3 = acc[mt][nt][3];
                v0 = v0 / (1.0f + __expf(-v0));
                v1 = v1 / (1.0f + __expf(-v1));
                v2 = v2 / (1.0f + __expf(-v2));
                v3 = v3 / (1.0f + __expf(-v3));
                __half2 h01 = __floats2half2_rn(v0, v1);
                __half2 h23 = __floats2half2_rn(v2, v3);
                *reinterpret_cast<__half2*>(&g_hbuf[(size_t)r0 * FDIM + c]) = h01;
                *reinterpret_cast<__half2*>(&g_hbuf[(size_t)(r0 + 8) * FDIM + c]) = h23;
            }
        }
    } else {
#pragma unroll
        for (int mt = 0; mt < 4; mt++) {
            int r0 = rbase + mt * 16 + rl;
            float w0 = g_row_w[r0];
            float w1 = g_row_w[r0 + 8];
#pragma unroll
            for (int nt = 0; nt < 8; nt++) {
                int c = cbase + nt * 8 + cl;
                float2 p0 = make_float2(acc[mt][nt][0] * w0, acc[mt][nt][1] * w0);
                float2 p1 = make_float2(acc[mt][nt][2] * w1, acc[mt][nt][3] * w1);
                *reinterpret_cast<float2*>(&g_yh[(size_t)r0 * HDIM + c]) = p0;
                *reinterpret_cast<float2*>(&g_yh[(size_t)(r0 + 8) * HDIM + c]) = p1;
            }
        }
    }
}

// ---------------- launch ----------------
extern "C" void kernel_launch(void* const* d_in, const int* in_sizes, int n_in,
                              void* d_out, int out_size) {
    const float* x  = (const float*)d_in[0];
    const int*   te = (const int*)d_in[1];
    const float* tw = (const float*)d_in[2];
    const float* w1 = (const float*)d_in[3];
    const float* w2 = (const float*)d_in[4];
    float* out = (float*)d_out;

    cudaFuncSetAttribute(gemm_kernel, cudaFuncAttributeMaxDynamicSharedMemorySize,
                         SMEM_TOTAL);

    routing_kernel<<<1, 256>>>(te);
    fill_kernel<<<NPAIR / 256, 256>>>(te, tw);
    gather_kernel<<<NPAIR, 256>>>(x);
    convert_w1_kernel<<<32768, 256>>>(w1);    // 8*4096*1024/4 float4s
    // layer-1 GEMM + fused w2 conversion (extra grid.y rows)
    gemm_kernel<<<dim3(FDIM / 128, MTILE_MAX + CONV_ROWS), 128, SMEM_TOTAL>>>(0, w2);
    gemm_kernel<<<dim3(HDIM / 128, MTILE_MAX), 128, SMEM_TOTAL>>>(1, w2);
    combine_kernel<<<S_TOK, 256>>>(out);
}

// round 15
// speedup vs baseline: 1.2036x; 1.0296x over previous
#include <cuda_runtime.h>
#include <cuda_fp16.h>
#include <cstdint>
#include <cstddef>

// ---------------- problem constants ----------------
#define S_TOK   8192
#define HDIM    1024
#define FDIM    4096
#define NEXP    8
#define NPAIR   16384              // S*K rows (one per (s,k) pair, no dedup)
#define ROWS_PAD 17408             // NPAIR + 8*127 rounded up
#define MTILE_MAX 144              // worst-case per-expert 128-row tiles (<=135)
#define CONV_ROWS 64               // extra grid.y rows in gemm1 that convert w2
#define CONV1_BLOCKS 4096          // extra blocks in gather launch converting w1

// GEMM tile: BM=128, BN=128, BK=64, 3-stage cp.async pipeline, mma.sync core
// 8 warps (256 threads), warp tile 64x32, occ 2  (R12 proven config)
// smem stage: A 128x128B + B 128x128B, XOR-swizzled 16B chunks (chunk ^= row&7)
#define A_STG  16384
#define STAGE_BYTES 32768
#define SMEM_TOTAL  (3 * STAGE_BYTES)          // 98304

// ---------------- device scratch (allocation-free rule) ----------------
__device__ __half g_xg  [(size_t)ROWS_PAD * HDIM];
__device__ __half g_hbuf[(size_t)ROWS_PAD * FDIM];
__device__ float  g_yh  [(size_t)ROWS_PAD * HDIM];
__device__ __half g_w1h [(size_t)NEXP * FDIM * HDIM];
__device__ __half g_w2h [(size_t)NEXP * FDIM * HDIM];
__device__ float  g_row_w[ROWS_PAD];
__device__ int    g_tok_rows[NPAIR];
__device__ int    g_tile_e[MTILE_MAX];
__device__ int    g_tile_m[MTILE_MAX];
__device__ int    g_nmt;

// ---------------- PTX helpers ----------------
__device__ __forceinline__ uint32_t smem_u32(const void* p) {
    uint32_t a;
    asm("{ .reg .u64 t; cvta.to.shared.u64 t, %1; cvt.u32.u64 %0, t; }"
        : "=r"(a) : "l"(p));
    return a;
}

__device__ __forceinline__ void cp16(uint32_t dst, const void* src) {
    asm volatile("cp.async.cg.shared.global [%0], [%1], 16;"
                 :: "r"(dst), "l"(src));
}

__device__ __forceinline__ void ldsm4(uint32_t* r, uint32_t a) {
    asm volatile("ldmatrix.sync.aligned.m8n8.x4.shared.b16 {%0,%1,%2,%3}, [%4];"
                 : "=r"(r[0]), "=r"(r[1]), "=r"(r[2]), "=r"(r[3]) : "r"(a));
}

__device__ __forceinline__ void mma16816(float* c, const uint32_t* a,
                                         uint32_t b0, uint32_t b1) {
    asm volatile(
        "mma.sync.aligned.m16n8k16.row.col.f32.f16.f16.f32 "
        "{%0,%1,%2,%3}, {%4,%5,%6,%7}, {%8,%9}, {%0,%1,%2,%3};"
        : "+f"(c[0]), "+f"(c[1]), "+f"(c[2]), "+f"(c[3])
        : "r"(a[0]), "r"(a[1]), "r"(a[2]), "r"(a[3]), "r"(b0), "r"(b1));
}

// ---------------- routing + fill (single block) ----------------
__global__ void routing_kernel(const int* __restrict__ te,
                               const float* __restrict__ tw) {
    __shared__ int scnt[NEXP];
    __shared__ int sbase[NEXP];
    __shared__ int sfill[NEXP];
    int tid = threadIdx.x;
    if (tid < NEXP) scnt[tid] = 0;
    __syncthreads();
    for (int t = tid; t < NPAIR; t += 256)
        atomicAdd(&scnt[((unsigned)te[t]) & 7u], 1);
    __syncthreads();
    if (tid == 0) {
        int base = 0, nt = 0;
        for (int e = 0; e < NEXP; e++) {
            sbase[e] = base;
            sfill[e] = 0;
            int tiles = (scnt[e] + 127) >> 7;
            for (int t = 0; t < tiles; t++) {
                g_tile_e[nt] = e;
                g_tile_m[nt] = base + t * 128;
                nt++;
            }
            base += tiles << 7;
        }
        g_nmt = nt;
    }
    __syncthreads();
    for (int t = tid; t < NPAIR; t += 256) {
        int e = ((unsigned)te[t]) & 7u;
        int pos = atomicAdd(&sfill[e], 1);
        int row = sbase[e] + pos;
        g_tok_rows[t] = row;
        g_row_w[row] = tw[t];
    }
}

// gather x rows (fp32 -> fp16) into grouped buffer (blocks [0, NPAIR)),
// plus w1 fp32->fp16 conversion (blocks [NPAIR, NPAIR+CONV1_BLOCKS)) running
// concurrently — the two roles touch disjoint data.
__global__ void gather_conv_kernel(const float* __restrict__ x,
                                   const float* __restrict__ w1) {
    int p = blockIdx.x;
    if (p >= NPAIR) {
        // w1 convert role: 8.4M float4 over CONV1_BLOCKS blocks (8 per thread)
        size_t tbase = (size_t)(p - NPAIR) * 256 + threadIdx.x;
        const float4* src = reinterpret_cast<const float4*>(w1);
#pragma unroll 4
        for (int j = 0; j < 8; j++) {
            size_t idx = tbase + (size_t)j * ((size_t)CONV1_BLOCKS * 256);
            float4 v = src[idx];
            __half2 a = __floats2half2_rn(v.x, v.y);
            __half2 b = __floats2half2_rn(v.z, v.w);
            uint2 u = make_uint2(*(uint32_t*)&a, *(uint32_t*)&b);
            *reinterpret_cast<uint2*>(&g_w1h[idx * 4]) = u;
        }
        return;
    }
    int j = threadIdx.x;                       // float4 index within row (256)
    int row = g_tok_rows[p];
    int s = p >> 1;
    float4 v = reinterpret_cast<const float4*>(x)[(size_t)s * 256 + j];
    __half2 a = __floats2half2_rn(v.x, v.y);
    __half2 b = __floats2half2_rn(v.z, v.w);
    uint2 u = make_uint2(*(uint32_t*)&a, *(uint32_t*)&b);
    *reinterpret_cast<uint2*>(&g_xg[(size_t)row * HDIM + j * 4]) = u;
}

// y[s] = yh[row(s,0)] + yh[row(s,1)]   (fixed order -> deterministic)
__global__ void combine_kernel(float* __restrict__ out) {
    int s = blockIdx.x, j = threadIdx.x;
    int r0 = g_tok_rows[2 * s];
    int r1 = g_tok_rows[2 * s + 1];
    const float4* Y = reinterpret_cast<const float4*>(g_yh);
    float4 a = Y[(size_t)r0 * 256 + j];
    float4 b = Y[(size_t)r1 * 256 + j];
    reinterpret_cast<float4*>(out)[(size_t)s * 256 + j] =
        make_float4(a.x + b.x, a.y + b.y, a.z + b.z, a.w + b.w);
}

// ---------------- grouped GEMM (mma.sync + cp.async, BK=64, 3 stages) ----------------
// mode 0: h = silu(Xg @ W1[e]^T) -> g_hbuf fp16    (lda=1024, kiter=16)
//         plus CONV_ROWS extra grid.y rows converting w2 fp32->fp16
// mode 1: y = (h @ W2[e]^T) * w  -> g_yh  fp32     (lda=4096, kiter=64)

// full-stage load (prologue only)
__device__ __forceinline__ void load_stage(uint32_t stg, int chunk,
                                           const __half* A, const __half* B,
                                           int lda, int tid) {
    uint32_t base = stg + (uint32_t)(chunk % 3) * STAGE_BYTES;
    const __half* Ap = A + chunk * 64;
    const __half* Bp = B + chunk * 64;
#pragma unroll
    for (int i = 0; i < 4; i++) {                 // A: 128 rows x 8 x 16B chunks
        int q = i * 256 + tid;
        int r = q >> 3, c = q & 7;
        uint32_t dst = base + (uint32_t)(r * 128 + ((c ^ (r & 7)) << 4));
        cp16(dst, Ap + (size_t)r * lda + c * 8);
    }
#pragma unroll
    for (int i = 0; i < 4; i++) {                 // B: 128 rows x 8 x 16B chunks
        int q = i * 256 + tid;
        int r = q >> 3, c = q & 7;
        uint32_t dst = base + A_STG + (uint32_t)(r * 128 + ((c ^ (r & 7)) << 4));
        cp16(dst, Bp + (size_t)r * lda + c * 8);
    }
    asm volatile("cp.async.commit_group;" ::: "memory");
}

// quarter-stage load: 1 A-chunk + 1 B-chunk per thread, issued once per ks step
__device__ __forceinline__ void load_quarter(uint32_t stg, int chunk, int ks,
                                             const __half* A, const __half* B,
                                             int lda, int tid) {
    uint32_t base = stg + (uint32_t)(chunk % 3) * STAGE_BYTES;
    const __half* Ap = A + chunk * 64;
    const __half* Bp = B + chunk * 64;
    int q = ks * 256 + tid;
    int r = q >> 3, c = q & 7;
    uint32_t da = base + (uint32_t)(r * 128 + ((c ^ (r & 7)) << 4));
    cp16(da, Ap + (size_t)r * lda + c * 8);
    uint32_t db = base + A_STG + (uint32_t)(r * 128 + ((c ^ (r & 7)) << 4));
    cp16(db, Bp + (size_t)r * lda + c * 8);
}

__global__ void __launch_bounds__(256, 2) gemm_kernel(int mode, const float* w2src) {
    // ---- fused w2 converter role (layer-1 launch only) ----
    if (mode == 0 && blockIdx.y >= MTILE_MAX) {
        size_t cid = (size_t)(blockIdx.y - MTILE_MAX) * gridDim.x + blockIdx.x;
        size_t tbase = cid * 256 + threadIdx.x;            // 0 .. 524287
        const float4* src = reinterpret_cast<const float4*>(w2src);
#pragma unroll 4
        for (int j = 0; j < 16; j++) {                     // 524288*16 = 8388608 float4
            size_t idx = tbase + (size_t)j * ((size_t)CONV_ROWS * 32 * 256);
            float4 v = src[idx];
            __half2 a = __floats2half2_rn(v.x, v.y);
            __half2 b = __floats2half2_rn(v.z, v.w);
            uint2 u = make_uint2(*(uint32_t*)&a, *(uint32_t*)&b);
            *reinterpret_cast<uint2*>(&g_w2h[idx * 4]) = u;
        }
        return;
    }

    int mt_idx = blockIdx.y;
    if (mt_idx >= g_nmt) return;

    const int lda   = mode ? FDIM : HDIM;
    const int kiter = mode ? (FDIM / 64) : (HDIM / 64);
    int m_base = g_tile_m[mt_idx];
    int n_base = blockIdx.x * 128;
    const __half* A = (mode ? g_hbuf : g_xg) + (size_t)m_base * lda;
    const __half* B = (mode ? g_w2h : g_w1h)
                      + (size_t)g_tile_e[mt_idx] * ((size_t)FDIM * HDIM)
                      + (size_t)n_base * lda;

    int tid = threadIdx.x;
    int wid = tid >> 5, lid = tid & 31;
    int warp_m = wid & 1;          // 2 along M  -> 64 rows each
    int warp_n = wid >> 1;         // 4 along N  -> 32 cols each

    extern __shared__ char smem[];
    uint32_t stg = smem_u32(smem);

    // ldmatrix lane addressing (same fragment mapping as the passing R10/R12 kernels)
    int ar = (lid & 7) + ((lid >> 3) & 1) * 8;   // row within 16-row tile
    int ac = (lid >> 4) & 1;                     // 16B k-chunk select
    int br = (lid & 7) + ((lid >> 4) & 1) * 8;   // row within 16-row n-pair
    int bc = (lid >> 3) & 1;

    float acc[4][4][4];
#pragma unroll
    for (int mt = 0; mt < 4; mt++)
#pragma unroll
        for (int nt = 0; nt < 4; nt++)
#pragma unroll
            for (int i = 0; i < 4; i++) acc[mt][nt][i] = 0.0f;

    // prologue: 2 stages in flight
    load_stage(stg, 0, A, B, lda, tid);
    load_stage(stg, 1, A, B, lda, tid);

    for (int k = 0; k < kiter; k++) {
        if (k + 2 < kiter) asm volatile("cp.async.wait_group 1;" ::: "memory");
        else               asm volatile("cp.async.wait_group 0;" ::: "memory");
        __syncthreads();

        bool pref = (k + 2 < kiter);
        uint32_t a_s = stg + (uint32_t)(k % 3) * STAGE_BYTES;
        uint32_t b_s = a_s + A_STG;

#pragma unroll
        for (int ks = 0; ks < 4; ks++) {          // four k16 steps per BK=64
            uint32_t af[4][4];
#pragma unroll
            for (int mt = 0; mt < 4; mt++) {
                int row = warp_m * 64 + mt * 16 + ar;
                int ch  = (ks * 2 + ac) ^ (row & 7);
                ldsm4(af[mt], a_s + (uint32_t)(row * 128 + (ch << 4)));
            }
            uint32_t bf[2][4];                    // each x4 covers 2 n-tiles
#pragma unroll
            for (int np = 0; np < 2; np++) {
                int row = warp_n * 32 + np * 16 + br;
                int ch  = (ks * 2 + bc) ^ (row & 7);
                ldsm4(bf[np], b_s + (uint32_t)(row * 128 + (ch << 4)));
            }
            // spread next-stage cp.async into the ldsm->MMA dependency gap
            if (pref) load_quarter(stg, k + 2, ks, A, B, lda, tid);
#pragma unroll
            for (int mt = 0; mt < 4; mt++) {
#pragma unroll
                for (int nt = 0; nt < 4; nt++) {
                    mma16816(acc[mt][nt], af[mt],
                             bf[nt >> 1][(nt & 1) * 2],
                             bf[nt >> 1][(nt & 1) * 2 + 1]);
                }
            }
        }
        if (pref) asm volatile("cp.async.commit_group;" ::: "memory");
    }
    __syncthreads();

    // ---------------- epilogue ----------------
    int rbase = m_base + warp_m * 64;
    int cbase = n_base + warp_n * 32;
    int rl = lid >> 2;                  // 0..7
    int cl = (lid & 3) * 2;             // 0,2,4,6

    if (mode == 0) {
#pragma unroll
        for (int mt = 0; mt < 4; mt++) {
            int r0 = rbase + mt * 16 + rl;
#pragma unroll
            for (int nt = 0; nt < 4; nt++) {
                int c = cbase + nt * 8 + cl;
                float v0 = acc[mt][nt][0], v1 = acc[mt][nt][1];
                float v2 = acc[mt][nt][2], v3 = acc[mt][nt][3];
                v0 = v0 / (1.0f + __expf(-v0));
                v1 = v1 / (1.0f + __expf(-v1));
                v2 = v2 / (1.0f + __expf(-v2));
                v3 = v3 / (1.0f + __expf(-v3));
                __half2 h01 = __floats2half2_rn(v0, v1);
                __half2 h23 = __floats2half2_rn(v2, v3);
                *reinterpret_cast<__half2*>(&g_hbuf[(size_t)r0 * FDIM + c]) = h01;
                *reinterpret_cast<__half2*>(&g_hbuf[(size_t)(r0 + 8) * FDIM + c]) = h23;
            }
        }
    } else {
#pragma unroll
        for (int mt = 0; mt < 4; mt++) {
            int r0 = rbase + mt * 16 + rl;
            float w0 = g_row_w[r0];
            float w1 = g_row_w[r0 + 8];
#pragma unroll
            for (int nt = 0; nt < 4; nt++) {
                int c = cbase + nt * 8 + cl;
                float2 p0 = make_float2(acc[mt][nt][0] * w0, acc[mt][nt][1] * w0);
                float2 p1 = make_float2(acc[mt][nt][2] * w1, acc[mt][nt][3] * w1);
                *reinterpret_cast<float2*>(&g_yh[(size_t)r0 * HDIM + c]) = p0;
                *reinterpret_cast<float2*>(&g_yh[(size_t)(r0 + 8) * HDIM + c]) = p1;
            }
        }
    }
}

// ---------------- launch ----------------
extern "C" void kernel_launch(void* const* d_in, const int* in_sizes, int n_in,
                              void* d_out, int out_size) {
    const float* x  = (const float*)d_in[0];
    const int*   te = (const int*)d_in[1];
    const float* tw = (const float*)d_in[2];
    const float* w1 = (const float*)d_in[3];
    const float* w2 = (const float*)d_in[4];
    float* out = (float*)d_out;

    cudaFuncSetAttribute(gemm_kernel, cudaFuncAttributeMaxDynamicSharedMemorySize,
                         SMEM_TOTAL);

    routing_kernel<<<1, 256>>>(te, tw);                       // count+sched+fill
    gather_conv_kernel<<<NPAIR + CONV1_BLOCKS, 256>>>(x, w1); // gather || w1 convert
    // layer-1 GEMM + fused w2 conversion (extra grid.y rows)
    gemm_kernel<<<dim3(FDIM / 128, MTILE_MAX + CONV_ROWS), 256, SMEM_TOTAL>>>(0, w2);
    gemm_kernel<<<dim3(HDIM / 128, MTILE_MAX), 256, SMEM_TOTAL>>>(1, w2);
    combine_kernel<<<S_TOK, 256>>>(out);
}

// round 16
// speedup vs baseline: 1.2635x; 1.0497x over previous
#include <cuda_runtime.h>
#include <cuda_fp16.h>
#include <cstdint>
#include <cstddef>

// ---------------- problem constants ----------------
#define S_TOK   8192
#define HDIM    1024
#define FDIM    4096
#define NEXP    8
#define NPAIR   16384              // S*K rows (one per (s,k) pair, no dedup)
#define ROWS_PAD 17408             // NPAIR + 8*127 rounded up
#define MTILE_MAX 144              // worst-case per-expert 128-row tiles (<=135)
#define CONV_ROWS 64               // extra grid.y rows in gemm1 that convert w2
#define CONV1_BLOCKS 4096          // extra blocks in gather launch converting w1

// GEMM tile: BM=128, BN=128, BK=64, 3-stage cp.async pipeline, mma.sync core
// 8 warps (256 threads), warp tile 64x32, occ 2  (R12 proven config)
// smem stage: A 128x128B + B 128x128B, XOR-swizzled 16B chunks (chunk ^= row&7)
#define A_STG  16384
#define STAGE_BYTES 32768
#define SMEM_TOTAL  (3 * STAGE_BYTES)          // 98304

// ---------------- device scratch (allocation-free rule) ----------------
__device__ __half g_xg  [(size_t)ROWS_PAD * HDIM];
__device__ __half g_hbuf[(size_t)ROWS_PAD * FDIM];
__device__ float  g_yh  [(size_t)ROWS_PAD * HDIM];
__device__ __half g_w1h [(size_t)NEXP * FDIM * HDIM];
__device__ __half g_w2h [(size_t)NEXP * FDIM * HDIM];
__device__ float  g_row_w[ROWS_PAD];
__device__ int    g_tok_rows[NPAIR];
__device__ int    g_tile_e[MTILE_MAX];
__device__ int    g_tile_m[MTILE_MAX];
__device__ int    g_nmt;

// ---------------- PTX helpers ----------------
__device__ __forceinline__ uint32_t smem_u32(const void* p) {
    uint32_t a;
    asm("{ .reg .u64 t; cvta.to.shared.u64 t, %1; cvt.u32.u64 %0, t; }"
        : "=r"(a) : "l"(p));
    return a;
}

__device__ __forceinline__ void cp16(uint32_t dst, const void* src) {
    asm volatile("cp.async.cg.shared.global [%0], [%1], 16;"
                 :: "r"(dst), "l"(src));
}

__device__ __forceinline__ void ldsm4(uint32_t* r, uint32_t a) {
    asm volatile("ldmatrix.sync.aligned.m8n8.x4.shared.b16 {%0,%1,%2,%3}, [%4];"
                 : "=r"(r[0]), "=r"(r[1]), "=r"(r[2]), "=r"(r[3]) : "r"(a));
}

__device__ __forceinline__ void mma16816(float* c, const uint32_t* a,
                                         uint32_t b0, uint32_t b1) {
    asm volatile(
        "mma.sync.aligned.m16n8k16.row.col.f32.f16.f16.f32 "
        "{%0,%1,%2,%3}, {%4,%5,%6,%7}, {%8,%9}, {%0,%1,%2,%3};"
        : "+f"(c[0]), "+f"(c[1]), "+f"(c[2]), "+f"(c[3])
        : "r"(a[0]), "r"(a[1]), "r"(a[2]), "r"(a[3]), "r"(b0), "r"(b1));
}

// ---------------- routing + fill (single block) ----------------
__global__ void routing_kernel(const int* __restrict__ te,
                               const float* __restrict__ tw) {
    __shared__ int scnt[NEXP];
    __shared__ int sbase[NEXP];
    __shared__ int sfill[NEXP];
    int tid = threadIdx.x;
    if (tid < NEXP) scnt[tid] = 0;
    __syncthreads();
    for (int t = tid; t < NPAIR; t += 256)
        atomicAdd(&scnt[((unsigned)te[t]) & 7u], 1);
    __syncthreads();
    if (tid == 0) {
        int base = 0, nt = 0;
        for (int e = 0; e < NEXP; e++) {
            sbase[e] = base;
            sfill[e] = 0;
            int tiles = (scnt[e] + 127) >> 7;
            for (int t = 0; t < tiles; t++) {
                g_tile_e[nt] = e;
                g_tile_m[nt] = base + t * 128;
                nt++;
            }
            base += tiles << 7;
        }
        g_nmt = nt;
    }
    __syncthreads();
    for (int t = tid; t < NPAIR; t += 256) {
        int e = ((unsigned)te[t]) & 7u;
        int pos = atomicAdd(&sfill[e], 1);
        int row = sbase[e] + pos;
        g_tok_rows[t] = row;
        g_row_w[row] = tw[t];
    }
}

// gather x rows (fp32 -> fp16) into grouped buffer (blocks [0, NPAIR)),
// plus w1 fp32->fp16 conversion (blocks [NPAIR, NPAIR+CONV1_BLOCKS)).
__global__ void gather_conv_kernel(const float* __restrict__ x,
                                   const float* __restrict__ w1) {
    int p = blockIdx.x;
    if (p >= NPAIR) {
        size_t tbase = (size_t)(p - NPAIR) * 256 + threadIdx.x;
        const float4* src = reinterpret_cast<const float4*>(w1);
#pragma unroll 4
        for (int j = 0; j < 8; j++) {
            size_t idx = tbase + (size_t)j * ((size_t)CONV1_BLOCKS * 256);
            float4 v = src[idx];
            __half2 a = __floats2half2_rn(v.x, v.y);
            __half2 b = __floats2half2_rn(v.z, v.w);
            uint2 u = make_uint2(*(uint32_t*)&a, *(uint32_t*)&b);
            *reinterpret_cast<uint2*>(&g_w1h[idx * 4]) = u;
        }
        return;
    }
    int j = threadIdx.x;                       // float4 index within row (256)
    int row = g_tok_rows[p];
    int s = p >> 1;
    float4 v = reinterpret_cast<const float4*>(x)[(size_t)s * 256 + j];
    __half2 a = __floats2half2_rn(v.x, v.y);
    __half2 b = __floats2half2_rn(v.z, v.w);
    uint2 u = make_uint2(*(uint32_t*)&a, *(uint32_t*)&b);
    *reinterpret_cast<uint2*>(&g_xg[(size_t)row * HDIM + j * 4]) = u;
}

// y[s] = yh[row(s,0)] + yh[row(s,1)]   (fixed order -> deterministic)
__global__ void combine_kernel(float* __restrict__ out) {
    int s = blockIdx.x, j = threadIdx.x;
    int r0 = g_tok_rows[2 * s];
    int r1 = g_tok_rows[2 * s + 1];
    const float4* Y = reinterpret_cast<const float4*>(g_yh);
    float4 a = Y[(size_t)r0 * 256 + j];
    float4 b = Y[(size_t)r1 * 256 + j];
    reinterpret_cast<float4*>(out)[(size_t)s * 256 + j] =
        make_float4(a.x + b.x, a.y + b.y, a.z + b.z, a.w + b.w);
}

// ---------------- grouped GEMM (mma.sync + cp.async, BK=64, 3 stages) ----------------
// mode 0: h = silu(Xg @ W1[e]^T) -> g_hbuf fp16    (lda=1024, kiter=16)
//         plus CONV_ROWS extra grid.y rows converting w2 fp32->fp16
// mode 1: y = (h @ W2[e]^T) * w  -> g_yh  fp32     (lda=4096, kiter=64)

// full-stage load (prologue only)
__device__ __forceinline__ void load_stage(uint32_t stg, int chunk,
                                           const __half* A, const __half* B,
                                           int lda, int tid) {
    uint32_t base = stg + (uint32_t)(chunk % 3) * STAGE_BYTES;
    const __half* Ap = A + chunk * 64;
    const __half* Bp = B + chunk * 64;
#pragma unroll
    for (int i = 0; i < 4; i++) {                 // A: 128 rows x 8 x 16B chunks
        int q = i * 256 + tid;
        int r = q >> 3, c = q & 7;
        uint32_t dst = base + (uint32_t)(r * 128 + ((c ^ (r & 7)) << 4));
        cp16(dst, Ap + (size_t)r * lda + c * 8);
    }
#pragma unroll
    for (int i = 0; i < 4; i++) {                 // B: 128 rows x 8 x 16B chunks
        int q = i * 256 + tid;
        int r = q >> 3, c = q & 7;
        uint32_t dst = base + A_STG + (uint32_t)(r * 128 + ((c ^ (r & 7)) << 4));
        cp16(dst, Bp + (size_t)r * lda + c * 8);
    }
    asm volatile("cp.async.commit_group;" ::: "memory");
}

__global__ void __launch_bounds__(256, 2) gemm_kernel(int mode, const float* w2src) {
    // ---- fused w2 converter role (layer-1 launch only) ----
    if (mode == 0 && blockIdx.y >= MTILE_MAX) {
        size_t cid = (size_t)(blockIdx.y - MTILE_MAX) * gridDim.x + blockIdx.x;
        size_t tbase = cid * 256 + threadIdx.x;            // 0 .. 524287
        const float4* src = reinterpret_cast<const float4*>(w2src);
#pragma unroll 4
        for (int j = 0; j < 16; j++) {                     // 524288*16 = 8388608 float4
            size_t idx = tbase + (size_t)j * ((size_t)CONV_ROWS * 32 * 256);
            float4 v = src[idx];
            __half2 a = __floats2half2_rn(v.x, v.y);
            __half2 b = __floats2half2_rn(v.z, v.w);
            uint2 u = make_uint2(*(uint32_t*)&a, *(uint32_t*)&b);
            *reinterpret_cast<uint2*>(&g_w2h[idx * 4]) = u;
        }
        return;
    }

    int mt_idx = blockIdx.y;
    if (mt_idx >= g_nmt) return;

    const int lda   = mode ? FDIM : HDIM;
    const int kiter = mode ? (FDIM / 64) : (HDIM / 64);
    int m_base = g_tile_m[mt_idx];
    int n_base = blockIdx.x * 128;
    const __half* A = (mode ? g_hbuf : g_xg) + (size_t)m_base * lda;
    const __half* B = (mode ? g_w2h : g_w1h)
                      + (size_t)g_tile_e[mt_idx] * ((size_t)FDIM * HDIM)
                      + (size_t)n_base * lda;

    int tid = threadIdx.x;
    int wid = tid >> 5, lid = tid & 31;
    int warp_m = wid & 1;          // 2 along M  -> 64 rows each
    int warp_n = wid >> 1;         // 4 along N  -> 32 cols each

    extern __shared__ char smem[];
    uint32_t stg = smem_u32(smem);

    // ldmatrix lane addressing (same fragment mapping as the passing R10/R12 kernels)
    int ar = (lid & 7) + ((lid >> 3) & 1) * 8;   // row within 16-row tile
    int ac = (lid >> 4) & 1;                     // 16B k-chunk select
    int br = (lid & 7) + ((lid >> 4) & 1) * 8;   // row within 16-row n-pair
    int bc = (lid >> 3) & 1;

    // --- precomputed ldsm smem offsets for ks=0 (XOR-rotated between ks steps) ---
    uint32_t a_off[4], b_off[2];
#pragma unroll
    for (int mt = 0; mt < 4; mt++) {
        int row = warp_m * 64 + mt * 16 + ar;
        a_off[mt] = (uint32_t)(row * 128 + ((ac ^ (row & 7)) << 4));
    }
#pragma unroll
    for (int np = 0; np < 2; np++) {
        int row = warp_n * 32 + np * 16 + br;
        b_off[np] = (uint32_t)(row * 128 + ((bc ^ (row & 7)) << 4) + A_STG);
    }

    // --- precomputed cp.async addressing (ks delta: smem +4096, gmem +32*lda) ---
    int r0 = tid >> 3, c0 = tid & 7;
    uint32_t cp_off = (uint32_t)(r0 * 128 + ((c0 ^ (r0 & 7)) << 4));
    const __half* Ag = A + 2 * 64 + (size_t)r0 * lda + c0 * 8;  // chunk 2 start
    const __half* Bg = B + 2 * 64 + (size_t)r0 * lda + c0 * 8;
    const size_t g_step = (size_t)32 * lda;

    float acc[4][4][4];
#pragma unroll
    for (int mt = 0; mt < 4; mt++)
#pragma unroll
        for (int nt = 0; nt < 4; nt++)
#pragma unroll
            for (int i = 0; i < 4; i++) acc[mt][nt][i] = 0.0f;

    // prologue: 2 stages in flight
    load_stage(stg, 0, A, B, lda, tid);
    load_stage(stg, 1, A, B, lda, tid);

    // stage-base rotation registers (read = s0, write = s2)
    uint32_t s0 = stg, s1 = stg + STAGE_BYTES, s2 = stg + 2 * STAGE_BYTES;

    for (int k = 0; k < kiter; k++) {
        if (k + 2 < kiter) asm volatile("cp.async.wait_group 1;" ::: "memory");
        else               asm volatile("cp.async.wait_group 0;" ::: "memory");
        __syncthreads();

        bool pref = (k + 2 < kiter);
        uint32_t aa0 = s0 + a_off[0], aa1 = s0 + a_off[1];
        uint32_t aa2 = s0 + a_off[2], aa3 = s0 + a_off[3];
        uint32_t bb0 = s0 + b_off[0], bb1 = s0 + b_off[1];
        uint32_t wa = s2 + cp_off;            // A write addr (ks=0)
        uint32_t wb = wa + A_STG;             // B write addr (ks=0)
        const __half* Aq = Ag;
        const __half* Bq = Bg;

#pragma unroll
        for (int ks = 0; ks < 4; ks++) {          // four k16 steps per BK=64
            uint32_t af[4][4];
            ldsm4(af[0], aa0);
            ldsm4(af[1], aa1);
            ldsm4(af[2], aa2);
            ldsm4(af[3], aa3);
            uint32_t bf[2][4];                    // each x4 covers 2 n-tiles
            ldsm4(bf[0], bb0);
            ldsm4(bf[1], bb1);
            // spread next-stage cp.async into the ldsm->MMA dependency gap
            if (pref) {
                cp16(wa + ks * 4096u, Aq);
                cp16(wb + ks * 4096u, Bq);
                Aq += g_step;
                Bq += g_step;
            }
#pragma unroll
            for (int mt = 0; mt < 4; mt++) {
#pragma unroll
                for (int nt = 0; nt < 4; nt++) {
                    mma16816(acc[mt][nt], af[mt],
                             bf[nt >> 1][(nt & 1) * 2],
                             bf[nt >> 1][(nt & 1) * 2 + 1]);
                }
            }
            if (ks < 3) {
                // swizzle-chunk XOR rotation: v=ks*2+c, v^(v+2) = 2,6,2 (<<4)
                const uint32_t dlt = (ks == 1) ? 0x60u : 0x20u;
                aa0 ^= dlt; aa1 ^= dlt; aa2 ^= dlt; aa3 ^= dlt;
                bb0 ^= dlt; bb1 ^= dlt;
            }
        }
        if (pref) asm volatile("cp.async.commit_group;" ::: "memory");
        Ag += 64;
        Bg += 64;
        uint32_t t = s0; s0 = s1; s1 = s2; s2 = t;     // rotate stages
    }
    __syncthreads();

    // ---------------- epilogue ----------------
    int rbase = m_base + warp_m * 64;
    int cbase = n_base + warp_n * 32;
    int rl = lid >> 2;                  // 0..7
    int cl = (lid & 3) * 2;             // 0,2,4,6

    if (mode == 0) {
#pragma unroll
        for (int mt = 0; mt < 4; mt++) {
            int r0e = rbase + mt * 16 + rl;
#pragma unroll
            for (int nt = 0; nt < 4; nt++) {
                int c = cbase + nt * 8 + cl;
                float v0 = acc[mt][nt][0], v1 = acc[mt][nt][1];
                float v2 = acc[mt][nt][2], v3 = acc[mt][nt][3];
                v0 = v0 / (1.0f + __expf(-v0));
                v1 = v1 / (1.0f + __expf(-v1));
                v2 = v2 / (1.0f + __expf(-v2));
                v3 = v3 / (1.0f + __expf(-v3));
                __half2 h01 = __floats2half2_rn(v0, v1);
                __half2 h23 = __floats2half2_rn(v2, v3);
                *reinterpret_cast<__half2*>(&g_hbuf[(size_t)r0e * FDIM + c]) = h01;
                *reinterpret_cast<__half2*>(&g_hbuf[(size_t)(r0e + 8) * FDIM + c]) = h23;
            }
        }
    } else {
#pragma unroll
        for (int mt = 0; mt < 4; mt++) {
            int r0e = rbase + mt * 16 + rl;
            float w0 = g_row_w[r0e];
            float w1 = g_row_w[r0e + 8];
#pragma unroll
            for (int nt = 0; nt < 4; nt++) {
                int c = cbase + nt * 8 + cl;
                float2 p0 = make_float2(acc[mt][nt][0] * w0, acc[mt][nt][1] * w0);
                float2 p1 = make_float2(acc[mt][nt][2] * w1, acc[mt][nt][3] * w1);
                *reinterpret_cast<float2*>(&g_yh[(size_t)r0e * HDIM + c]) = p0;
                *reinterpret_cast<float2*>(&g_yh[(size_t)(r0e + 8) * HDIM + c]) = p1;
            }
        }
    }
}

// ---------------- launch ----------------
extern "C" void kernel_launch(void* const* d_in, const int* in_sizes, int n_in,
                              void* d_out, int out_size) {
    const float* x  = (const float*)d_in[0];
    const int*   te = (const int*)d_in[1];
    const float* tw = (const float*)d_in[2];
    const float* w1 = (const float*)d_in[3];
    const float* w2 = (const float*)d_in[4];
    float* out = (float*)d_out;

    cudaFuncSetAttribute(gemm_kernel, cudaFuncAttributeMaxDynamicSharedMemorySize,
                         SMEM_TOTAL);

    routing_kernel<<<1, 256>>>(te, tw);                       // count+sched+fill
    gather_conv_kernel<<<NPAIR + CONV1_BLOCKS, 256>>>(x, w1); // gather || w1 convert
    // layer-1 GEMM + fused w2 conversion (extra grid.y rows)
    gemm_kernel<<<dim3(FDIM / 128, MTILE_MAX + CONV_ROWS), 256, SMEM_TOTAL>>>(0, w2);
    gemm_kernel<<<dim3(HDIM / 128, MTILE_MAX), 256, SMEM_TOTAL>>>(1, w2);
    combine_kernel<<<S_TOK, 256>>>(out);
}